// round 2
// baseline (speedup 1.0000x reference)
#include <cuda_runtime.h>

#define HW   16384      // 128*128
#define NPIX 32768      // B * HW
#define NCLS 35

// -------- device scratch (no allocs allowed) --------
__device__ int   d_cnt[NCLS];
__device__ int   d_prefix[NCLS + 1];
__device__ int   d_clist[NCLS * NPIX];     // 4.6 MB
__device__ float d_xt[NPIX * 64];          // x' pixel-major, 8.4 MB
__device__ float d_ysc[NPIX * 64];         // y  pixel-major, 8.4 MB
__device__ float d_sum[128];
__device__ float d_sq[128];

// -------- zero counters + moments (graph-replay safe) --------
__global__ void k_init() {
    int t = threadIdx.x;
    if (t < NCLS) d_cnt[t] = 0;
    if (t < 128) { d_sum[t] = 0.f; d_sq[t] = 0.f; }
}

// -------- kA: pos-scalar + argmax routing + transpose x' --------
__global__ void kA(const float* __restrict__ x, const float* __restrict__ layout,
                   const float* __restrict__ pr, const float* __restrict__ conv_w,
                   const float* __restrict__ conv_b, const float* __restrict__ pl) {
    __shared__ float tile[128 * 65];
    int t  = threadIdx.x;
    int p  = blockIdx.x * 128 + t;          // one pixel per thread
    int b  = p >> 14;
    int hw = p & (HW - 1);
    int i  = hw >> 7;      // row
    int j  = hw & 127;     // col

    // positional scalar: pa(2) + pl(2) + pr(2) + coords(4), then 1x1 conv + bias
    float px = (float)i * (2.0f / 128.0f) - 1.0f;
    float py = (float)j * (2.0f / 128.0f) - 1.0f;
    float pl0 = pl[hw], pl1 = pl[HW + hw];
    const float* prb = pr + b * 2 * HW;
    float pr0 = prb[hw], pr1 = prb[HW + hw];
    const float A23 = 2.0943951023931953f;   // 2*pi/3
    float ax = A23 * (float)(j % 3);
    float ay = A23 * (float)(i % 3);
    float s = px * conv_w[0] + py * conv_w[1] + pl0 * conv_w[2] + pl1 * conv_w[3]
            + pr0 * conv_w[4] + pr1 * conv_w[5]
            + cosf(ax) * conv_w[6] + sinf(ax) * conv_w[7]
            + cosf(ay) * conv_w[8] + sinf(ay) * conv_w[9] + conv_b[0];

    // argmax over 35 layout channels (first-max on ties: strict >)
    const float* lb = layout + (size_t)b * NCLS * HW + hw;
    float best = lb[0];
    int arg = 0;
    #pragma unroll
    for (int k = 1; k < NCLS; k++) {
        float v = lb[(size_t)k * HW];
        if (v > best) { best = v; arg = k; }
    }
    int slot = atomicAdd(&d_cnt[arg], 1);
    d_clist[arg * NPIX + slot] = p;

    // transpose x' = x + s  ->  xt[pixel][64]  (coalesced read, coalesced write)
    const float* xb = x + (size_t)b * 64 * HW + hw;
    #pragma unroll 8
    for (int c = 0; c < 64; c++) tile[t * 65 + c] = xb[(size_t)c * HW] + s;
    __syncthreads();

    int p0 = blockIdx.x * 128;
    #pragma unroll
    for (int r = 0; r < 16; r++) {
        int lin = r * 128 + t;
        int pp  = lin >> 4;
        int c4  = (lin & 15) << 2;
        float4 v;
        v.x = tile[pp * 65 + c4 + 0];
        v.y = tile[pp * 65 + c4 + 1];
        v.z = tile[pp * 65 + c4 + 2];
        v.w = tile[pp * 65 + c4 + 3];
        *(float4*)&d_xt[(size_t)(p0 + pp) * 64 + c4] = v;
    }
}

// -------- kA2: prefix of per-class block counts --------
__global__ void kA2() {
    if (threadIdx.x == 0) {
        int acc = 0;
        for (int k = 0; k < NCLS; k++) {
            d_prefix[k] = acc;
            acc += (d_cnt[k] + 63) >> 6;
        }
        d_prefix[NCLS] = acc;
    }
}

// -------- kB: grouped GEMM (class, 64-pixel chunk) + bias + moments --------
__global__ void kB(const float* __restrict__ Wt, const float* __restrict__ bt) {
    __shared__ float Wsm[64 * 64];
    __shared__ float xs[64 * 64];
    __shared__ float red[8 * 256];
    __shared__ float bsm[64];
    __shared__ int   pixs[64];
    __shared__ int   skc[2];

    int t   = threadIdx.x;
    int bid = blockIdx.x;
    int total = d_prefix[NCLS];
    if (bid >= total) return;

    if (t == 0) {
        int k = 0;
        while (d_prefix[k + 1] <= bid) k++;
        skc[0] = k;
        skc[1] = bid - d_prefix[k];
    }
    __syncthreads();
    int k    = skc[0];
    int base = skc[1] * 64;
    int n    = min(64, d_cnt[k] - base);

    // load expert matrix (16KB) + bias + pixel list
    const float4* Wk4  = (const float4*)(Wt + (size_t)k * 4096);
    float4*       Wsm4 = (float4*)Wsm;
    #pragma unroll
    for (int r = 0; r < 4; r++) Wsm4[r * 256 + t] = Wk4[r * 256 + t];
    if (t < 64) {
        bsm[t]  = bt[k * 64 + t];
        pixs[t] = (t < n) ? d_clist[k * NPIX + base + t] : -1;
    }
    __syncthreads();

    // gather x' rows (256B contiguous per pixel)
    float4* xs4 = (float4*)xs;
    #pragma unroll
    for (int r = 0; r < 4; r++) {
        int lin = r * 256 + t;
        int pp  = lin >> 4;
        int c4  = lin & 15;
        int pix = pixs[pp];
        float4 v = make_float4(0.f, 0.f, 0.f, 0.f);
        if (pix >= 0) v = ((const float4*)d_xt)[(size_t)pix * 16 + c4];
        xs4[pp * 16 + c4] = v;
    }
    __syncthreads();

    // 4 pixels x 4 outputs register tile per thread
    int og = t & 15;   // output quad
    int pg = t >> 4;   // pixel quad
    float acc[4][4];
    #pragma unroll
    for (int pp = 0; pp < 4; pp++)
        #pragma unroll
        for (int ii = 0; ii < 4; ii++) acc[pp][ii] = 0.f;

    #pragma unroll
    for (int c4 = 0; c4 < 16; c4++) {
        float4 w0 = Wsm4[(4 * c4 + 0) * 16 + og];
        float4 w1 = Wsm4[(4 * c4 + 1) * 16 + og];
        float4 w2 = Wsm4[(4 * c4 + 2) * 16 + og];
        float4 w3 = Wsm4[(4 * c4 + 3) * 16 + og];
        #pragma unroll
        for (int pp = 0; pp < 4; pp++) {
            float4 xv = xs4[(4 * pg + pp) * 16 + c4];
            acc[pp][0] += xv.x * w0.x + xv.y * w1.x + xv.z * w2.x + xv.w * w3.x;
            acc[pp][1] += xv.x * w0.y + xv.y * w1.y + xv.z * w2.y + xv.w * w3.y;
            acc[pp][2] += xv.x * w0.z + xv.y * w1.z + xv.z * w2.z + xv.w * w3.z;
            acc[pp][3] += xv.x * w0.w + xv.y * w1.w + xv.z * w2.w + xv.w * w3.w;
        }
    }

    float b0 = bsm[4 * og + 0], b1 = bsm[4 * og + 1];
    float b2 = bsm[4 * og + 2], b3 = bsm[4 * og + 3];

    float s0[4] = {0,0,0,0}, q0[4] = {0,0,0,0};   // batch 0 moments
    float s1[4] = {0,0,0,0}, q1[4] = {0,0,0,0};   // batch 1 moments
    #pragma unroll
    for (int pp = 0; pp < 4; pp++) {
        int pix = pixs[4 * pg + pp];
        if (pix >= 0) {
            float4 yv;
            yv.x = acc[pp][0] + b0;
            yv.y = acc[pp][1] + b1;
            yv.z = acc[pp][2] + b2;
            yv.w = acc[pp][3] + b3;
            ((float4*)d_ysc)[(size_t)pix * 16 + og] = yv;
            if (pix < HW) {
                s0[0] += yv.x; s0[1] += yv.y; s0[2] += yv.z; s0[3] += yv.w;
                q0[0] += yv.x * yv.x; q0[1] += yv.y * yv.y;
                q0[2] += yv.z * yv.z; q0[3] += yv.w * yv.w;
            } else {
                s1[0] += yv.x; s1[1] += yv.y; s1[2] += yv.z; s1[3] += yv.w;
                q1[0] += yv.x * yv.x; q1[1] += yv.y * yv.y;
                q1[2] += yv.z * yv.z; q1[3] += yv.w * yv.w;
            }
        }
    }

    // lanes l and l+16 share og -> pairwise reduce
    #pragma unroll
    for (int ii = 0; ii < 4; ii++) {
        s0[ii] += __shfl_xor_sync(0xffffffffu, s0[ii], 16);
        q0[ii] += __shfl_xor_sync(0xffffffffu, q0[ii], 16);
        s1[ii] += __shfl_xor_sync(0xffffffffu, s1[ii], 16);
        q1[ii] += __shfl_xor_sync(0xffffffffu, q1[ii], 16);
    }
    int w = t >> 5;
    if ((t & 31) < 16) {
        float* rr = &red[w * 256 + og * 16];
        #pragma unroll
        for (int ii = 0; ii < 4; ii++) {
            rr[0  + ii] = s0[ii];
            rr[4  + ii] = q0[ii];
            rr[8  + ii] = s1[ii];
            rr[12 + ii] = q1[ii];
        }
    }
    __syncthreads();
    {
        int ogl = t >> 4;
        int jj  = t & 15;
        float v = 0.f;
        #pragma unroll
        for (int ww = 0; ww < 8; ww++) v += red[ww * 256 + ogl * 16 + jj];
        int bb  = jj >> 3;
        int isq = (jj >> 2) & 1;
        int ii  = jj & 3;
        int chan = bb * 64 + ogl * 4 + ii;
        if (isq) atomicAdd(&d_sq[chan], v);
        else     atomicAdd(&d_sum[chan], v);
    }
}

// -------- kC: instance norm + leaky + transpose to (B,C,H,W) --------
__global__ void kC(float* __restrict__ out) {
    __shared__ float tile[8][32][33];
    int t = threadIdx.x;
    int w = t >> 5, lane = t & 31;
    int p0    = blockIdx.x * 128;          // 128 pixels per block (single batch)
    int b     = p0 >> 14;
    int hw0   = p0 & (HW - 1);
    int c0    = (w & 1) * 32;
    int pbase = (w >> 1) * 32;

    int chan   = b * 64 + c0 + lane;
    float mean = d_sum[chan] * (1.0f / 16384.0f);
    float var  = d_sq[chan] * (1.0f / 16384.0f) - mean * mean;
    float rstd = rsqrtf(var + 1e-5f);

    #pragma unroll
    for (int r = 0; r < 32; r++) {
        float v = d_ysc[(size_t)(p0 + pbase + r) * 64 + c0 + lane];
        v = (v - mean) * rstd;
        v = v >= 0.f ? v : 0.01f * v;
        tile[w][r][lane] = v;
    }
    __syncwarp();
    #pragma unroll
    for (int r = 0; r < 32; r++) {
        out[(size_t)(b * 64 + c0 + r) * HW + hw0 + pbase + lane] = tile[w][lane][r];
    }
}

extern "C" void kernel_launch(void* const* d_in, const int* in_sizes, int n_in,
                              void* d_out, int out_size) {
    const float* x      = (const float*)d_in[0];
    const float* layout = (const float*)d_in[1];
    const float* pr     = (const float*)d_in[2];
    const float* conv_w = (const float*)d_in[3];
    const float* conv_b = (const float*)d_in[4];
    const float* Wt     = (const float*)d_in[5];
    const float* bt     = (const float*)d_in[6];
    const float* pl     = (const float*)d_in[7];
    float* out = (float*)d_out;

    k_init<<<1, 128>>>();
    kA<<<256, 128>>>(x, layout, pr, conv_w, conv_b, pl);
    kA2<<<1, 32>>>();
    kB<<<547, 256>>>(Wt, bt);   // 547 >= max total (class,chunk) blocks
    kC<<<256, 256>>>(out);
}

// round 3
// speedup vs baseline: 1.0544x; 1.0544x over previous
#include <cuda_runtime.h>

#define HW   16384      // 128*128
#define NPIX 32768      // B * HW
#define NCLS 35

// -------- device scratch (no allocs allowed) --------
__device__ int   d_cnt[NCLS];
__device__ int   d_prefix[NCLS + 1];
__device__ int   d_clist[NCLS * NPIX];     // 4.6 MB
__device__ float d_xt[NPIX * 64];          // x' pixel-major, 8.4 MB
__device__ float d_ysc[NPIX * 64];         // y  pixel-major, 8.4 MB
__device__ float d_sum[128];
__device__ float d_sq[128];

// -------- zero counters + moments (graph-replay safe) --------
__global__ void k_init() {
    int t = threadIdx.x;
    if (t < NCLS) d_cnt[t] = 0;
    if (t < 128) { d_sum[t] = 0.f; d_sq[t] = 0.f; }
}

// -------- kA: pos-scalar + argmax routing + transpose x' --------
__global__ void kA(const float* __restrict__ x, const float* __restrict__ layout,
                   const float* __restrict__ pr, const float* __restrict__ conv_w,
                   const float* __restrict__ conv_b, const float* __restrict__ pl) {
    __shared__ float tile[128 * 65];
    int t  = threadIdx.x;
    int p  = blockIdx.x * 128 + t;          // one pixel per thread
    int b  = p >> 14;
    int hw = p & (HW - 1);
    int i  = hw >> 7;      // row
    int j  = hw & 127;     // col

    // positional scalar: pa(2) + pl(2) + pr(2) + coords(4), then 1x1 conv + bias
    float px = (float)i * (2.0f / 128.0f) - 1.0f;
    float py = (float)j * (2.0f / 128.0f) - 1.0f;
    float pl0 = pl[hw], pl1 = pl[HW + hw];
    const float* prb = pr + b * 2 * HW;
    float pr0 = prb[hw], pr1 = prb[HW + hw];
    const float A23 = 2.0943951023931953f;   // 2*pi/3
    float ax = A23 * (float)(j % 3);
    float ay = A23 * (float)(i % 3);
    float s = px * conv_w[0] + py * conv_w[1] + pl0 * conv_w[2] + pl1 * conv_w[3]
            + pr0 * conv_w[4] + pr1 * conv_w[5]
            + cosf(ax) * conv_w[6] + sinf(ax) * conv_w[7]
            + cosf(ay) * conv_w[8] + sinf(ay) * conv_w[9] + conv_b[0];

    // argmax over 35 layout channels (first-max on ties: strict >)
    const float* lb = layout + (size_t)b * NCLS * HW + hw;
    float best = lb[0];
    int arg = 0;
    #pragma unroll
    for (int k = 1; k < NCLS; k++) {
        float v = lb[(size_t)k * HW];
        if (v > best) { best = v; arg = k; }
    }
    int slot = atomicAdd(&d_cnt[arg], 1);
    d_clist[arg * NPIX + slot] = p;

    // transpose x' = x + s  ->  xt[pixel][64]  (coalesced read, coalesced write)
    const float* xb = x + (size_t)b * 64 * HW + hw;
    #pragma unroll 8
    for (int c = 0; c < 64; c++) tile[t * 65 + c] = xb[(size_t)c * HW] + s;
    __syncthreads();

    int p0 = blockIdx.x * 128;
    #pragma unroll
    for (int r = 0; r < 16; r++) {
        int lin = r * 128 + t;
        int pp  = lin >> 4;
        int c4  = (lin & 15) << 2;
        float4 v;
        v.x = tile[pp * 65 + c4 + 0];
        v.y = tile[pp * 65 + c4 + 1];
        v.z = tile[pp * 65 + c4 + 2];
        v.w = tile[pp * 65 + c4 + 3];
        *(float4*)&d_xt[(size_t)(p0 + pp) * 64 + c4] = v;
    }
}

// -------- kA2: prefix of per-class block counts --------
__global__ void kA2() {
    if (threadIdx.x == 0) {
        int acc = 0;
        for (int k = 0; k < NCLS; k++) {
            d_prefix[k] = acc;
            acc += (d_cnt[k] + 63) >> 6;
        }
        d_prefix[NCLS] = acc;
    }
}

// -------- kB: grouped GEMM (class, 64-pixel chunk) + bias + moments --------
__global__ void kB(const float* __restrict__ Wt, const float* __restrict__ bt) {
    __shared__ float Wsm[64 * 64];
    __shared__ float xs[64 * 64];
    __shared__ float red[8 * 256];
    __shared__ float bsm[64];
    __shared__ int   pixs[64];
    __shared__ int   skc[2];

    int t   = threadIdx.x;
    int bid = blockIdx.x;
    int total = d_prefix[NCLS];
    if (bid >= total) return;

    if (t == 0) {
        int k = 0;
        while (d_prefix[k + 1] <= bid) k++;
        skc[0] = k;
        skc[1] = bid - d_prefix[k];
    }
    __syncthreads();
    int k    = skc[0];
    int base = skc[1] * 64;
    int n    = min(64, d_cnt[k] - base);

    // load expert matrix (16KB) + bias + pixel list
    const float4* Wk4  = (const float4*)(Wt + (size_t)k * 4096);
    float4*       Wsm4 = (float4*)Wsm;
    #pragma unroll
    for (int r = 0; r < 4; r++) Wsm4[r * 256 + t] = Wk4[r * 256 + t];
    if (t < 64) {
        bsm[t]  = bt[k * 64 + t];
        pixs[t] = (t < n) ? d_clist[k * NPIX + base + t] : -1;
    }
    __syncthreads();

    // gather x' rows (256B contiguous per pixel)
    float4* xs4 = (float4*)xs;
    #pragma unroll
    for (int r = 0; r < 4; r++) {
        int lin = r * 256 + t;
        int pp  = lin >> 4;
        int c4  = lin & 15;
        int pix = pixs[pp];
        float4 v = make_float4(0.f, 0.f, 0.f, 0.f);
        if (pix >= 0) v = ((const float4*)d_xt)[(size_t)pix * 16 + c4];
        xs4[pp * 16 + c4] = v;
    }
    __syncthreads();

    // 4 pixels x 4 outputs register tile per thread
    int og = t & 15;   // output quad
    int pg = t >> 4;   // pixel quad
    float acc[4][4];
    #pragma unroll
    for (int pp = 0; pp < 4; pp++)
        #pragma unroll
        for (int ii = 0; ii < 4; ii++) acc[pp][ii] = 0.f;

    #pragma unroll
    for (int c4 = 0; c4 < 16; c4++) {
        float4 w0 = Wsm4[(4 * c4 + 0) * 16 + og];
        float4 w1 = Wsm4[(4 * c4 + 1) * 16 + og];
        float4 w2 = Wsm4[(4 * c4 + 2) * 16 + og];
        float4 w3 = Wsm4[(4 * c4 + 3) * 16 + og];
        #pragma unroll
        for (int pp = 0; pp < 4; pp++) {
            float4 xv = xs4[(4 * pg + pp) * 16 + c4];
            acc[pp][0] += xv.x * w0.x + xv.y * w1.x + xv.z * w2.x + xv.w * w3.x;
            acc[pp][1] += xv.x * w0.y + xv.y * w1.y + xv.z * w2.y + xv.w * w3.y;
            acc[pp][2] += xv.x * w0.z + xv.y * w1.z + xv.z * w2.z + xv.w * w3.z;
            acc[pp][3] += xv.x * w0.w + xv.y * w1.w + xv.z * w2.w + xv.w * w3.w;
        }
    }

    float b0 = bsm[4 * og + 0], b1 = bsm[4 * og + 1];
    float b2 = bsm[4 * og + 2], b3 = bsm[4 * og + 3];

    float s0[4] = {0,0,0,0}, q0[4] = {0,0,0,0};   // batch 0 moments
    float s1[4] = {0,0,0,0}, q1[4] = {0,0,0,0};   // batch 1 moments
    #pragma unroll
    for (int pp = 0; pp < 4; pp++) {
        int pix = pixs[4 * pg + pp];
        if (pix >= 0) {
            float4 yv;
            yv.x = acc[pp][0] + b0;
            yv.y = acc[pp][1] + b1;
            yv.z = acc[pp][2] + b2;
            yv.w = acc[pp][3] + b3;
            ((float4*)d_ysc)[(size_t)pix * 16 + og] = yv;
            if (pix < HW) {
                s0[0] += yv.x; s0[1] += yv.y; s0[2] += yv.z; s0[3] += yv.w;
                q0[0] += yv.x * yv.x; q0[1] += yv.y * yv.y;
                q0[2] += yv.z * yv.z; q0[3] += yv.w * yv.w;
            } else {
                s1[0] += yv.x; s1[1] += yv.y; s1[2] += yv.z; s1[3] += yv.w;
                q1[0] += yv.x * yv.x; q1[1] += yv.y * yv.y;
                q1[2] += yv.z * yv.z; q1[3] += yv.w * yv.w;
            }
        }
    }

    // lanes l and l+16 share og -> pairwise reduce
    #pragma unroll
    for (int ii = 0; ii < 4; ii++) {
        s0[ii] += __shfl_xor_sync(0xffffffffu, s0[ii], 16);
        q0[ii] += __shfl_xor_sync(0xffffffffu, q0[ii], 16);
        s1[ii] += __shfl_xor_sync(0xffffffffu, s1[ii], 16);
        q1[ii] += __shfl_xor_sync(0xffffffffu, q1[ii], 16);
    }
    int w = t >> 5;
    if ((t & 31) < 16) {
        float* rr = &red[w * 256 + og * 16];
        #pragma unroll
        for (int ii = 0; ii < 4; ii++) {
            rr[0  + ii] = s0[ii];
            rr[4  + ii] = q0[ii];
            rr[8  + ii] = s1[ii];
            rr[12 + ii] = q1[ii];
        }
    }
    __syncthreads();
    {
        int ogl = t >> 4;
        int jj  = t & 15;
        float v = 0.f;
        #pragma unroll
        for (int ww = 0; ww < 8; ww++) v += red[ww * 256 + ogl * 16 + jj];
        int bb  = jj >> 3;
        int isq = (jj >> 2) & 1;
        int ii  = jj & 3;
        int chan = bb * 64 + ogl * 4 + ii;
        if (isq) atomicAdd(&d_sq[chan], v);
        else     atomicAdd(&d_sum[chan], v);
    }
}

// -------- kC: instance norm + leaky + transpose to (B,C,H,W) --------
__global__ void kC(float* __restrict__ out) {
    __shared__ float tile[8][32][33];
    int t = threadIdx.x;
    int w = t >> 5, lane = t & 31;
    int p0    = blockIdx.x * 128;          // 128 pixels per block (single batch)
    int b     = p0 >> 14;
    int hw0   = p0 & (HW - 1);
    int c0    = (w & 1) * 32;
    int pbase = (w >> 1) * 32;

    int chan   = b * 64 + c0 + lane;
    float mean = d_sum[chan] * (1.0f / 16384.0f);
    float var  = d_sq[chan] * (1.0f / 16384.0f) - mean * mean;
    float rstd = rsqrtf(var + 1e-5f);

    #pragma unroll
    for (int r = 0; r < 32; r++) {
        float v = d_ysc[(size_t)(p0 + pbase + r) * 64 + c0 + lane];
        v = (v - mean) * rstd;
        v = v >= 0.f ? v : 0.01f * v;
        tile[w][r][lane] = v;
    }
    __syncwarp();
    #pragma unroll
    for (int r = 0; r < 32; r++) {
        out[(size_t)(b * 64 + c0 + r) * HW + hw0 + pbase + lane] = tile[w][lane][r];
    }
}

extern "C" void kernel_launch(void* const* d_in, const int* in_sizes, int n_in,
                              void* d_out, int out_size) {
    const float* x      = (const float*)d_in[0];
    const float* layout = (const float*)d_in[1];
    const float* pr     = (const float*)d_in[2];
    const float* conv_w = (const float*)d_in[3];
    const float* conv_b = (const float*)d_in[4];
    const float* Wt     = (const float*)d_in[5];
    const float* bt     = (const float*)d_in[6];
    const float* pl     = (const float*)d_in[7];
    float* out = (float*)d_out;

    k_init<<<1, 128>>>();
    kA<<<256, 128>>>(x, layout, pr, conv_w, conv_b, pl);
    kA2<<<1, 32>>>();
    kB<<<547, 256>>>(Wt, bt);   // 547 >= max total (class,chunk) blocks
    kC<<<256, 256>>>(out);
}